// round 1
// baseline (speedup 1.0000x reference)
#include <cuda_runtime.h>
#include <math.h>

#define POOL 7
#define CCH 256
#define HALF 128   // channels per block

struct BoxShared {
    const float* fm;
    long cbase;          // b * C * H * W
    int HW;              // H == W for each level
    int rows[3], cols[3];            // clamped global patch indices
    int ry0[POOL], ry1[POOL];        // per-bin row offsets into patch (0..2)
    int cx0[POOL], cx1[POOL];        // per-bin col offsets into patch (0..2)
    float ly[POOL], lx[POOL];        // bilinear fractions
    float vy[POOL], vx[POOL];        // validity masks (1.0 here, kept for fidelity)
};

__global__ void __launch_bounds__(HALF) roi_align_kernel(
    const float* __restrict__ boxes,
    const float* __restrict__ f2,
    const float* __restrict__ f3,
    const float* __restrict__ f4,
    const float* __restrict__ f5,
    float* __restrict__ out,
    int nboxes)
{
    __shared__ BoxShared S;
    __shared__ float patch[HALF][9];
    __shared__ __align__(16) float stage[HALF * POOL * POOL];

    const int box  = blockIdx.x >> 1;
    const int half = blockIdx.x & 1;
    const int tid  = threadIdx.x;

    if (tid == 0) {
        // columns: 0=batch, then (per reference roi_level calc) 1=y1,2=x1,3=y2,4=x2
        const float bf = boxes[box * 5 + 0];
        const float c1 = boxes[box * 5 + 1];
        const float c2 = boxes[box * 5 + 2];
        const float c3 = boxes[box * 5 + 3];
        const float c4 = boxes[box * 5 + 4];

        // roi level: 4 + log2(sqrt(h*w) / (224/1024)), round-half-even, clip [2,5]
        const float h = c3 - c1;
        const float w = c4 - c2;
        float lvlf = 4.0f + log2f(sqrtf(h * w) / 0.21875f);
        int lvl = (int)rintf(lvlf);
        lvl = max(2, min(5, lvl));

        const float* fm = (lvl == 2) ? f2 : (lvl == 3) ? f3 : (lvl == 4) ? f4 : f5;
        const int   H     = 1024 >> lvl;          // 256,128,64,32
        const float scale = 1.0f / (float)(1 << lvl);

        S.fm    = fm;
        S.HW    = H;
        S.cbase = (long)((int)bf) * CCH * H * H;

        // _roi_align uses rois = boxes[:,1:] with columns interpreted as
        // (x1, y1, x2, y2) — i.e. x comes from boxes cols 1,3 and y from 2,4.
        const float ax1 = c1 * scale, ay1 = c2 * scale;
        const float ax2 = c3 * scale, ay2 = c4 * scale;
        const float rw = fmaxf(ax2 - ax1, 1.0f);
        const float rh = fmaxf(ay2 - ay1, 1.0f);
        const float bw = rw / (float)POOL;
        const float bh = rh / (float)POOL;

        int X0 = 0, Y0 = 0;
        for (int p = 0; p < POOL; p++) {
            const float pc = (float)p + 0.5f;

            float y  = ay1 + pc * bh;
            float vy = (y > -1.0f && y < (float)H) ? 1.0f : 0.0f;
            float ycl = fminf(fmaxf(y, 0.0f), (float)(H - 1));
            int   y0  = (int)floorf(ycl);
            int   y1i = min(y0 + 1, H - 1);
            if (p == 0) Y0 = y0;               // xs/ys monotone increasing -> p=0 is min
            S.ry0[p] = y0 - Y0;
            S.ry1[p] = y1i - Y0;
            S.ly[p]  = ycl - (float)y0;
            S.vy[p]  = vy;

            float x  = ax1 + pc * bw;
            float vx = (x > -1.0f && x < (float)H) ? 1.0f : 0.0f;
            float xcl = fminf(fmaxf(x, 0.0f), (float)(H - 1));
            int   x0  = (int)floorf(xcl);
            int   x1i = min(x0 + 1, H - 1);
            if (p == 0) X0 = x0;
            S.cx0[p] = x0 - X0;
            S.cx1[p] = x1i - X0;
            S.lx[p]  = xcl - (float)x0;
            S.vx[p]  = vx;
        }
        // Patch spans at most 3x3 because the bin grid spans < 1 pixel (bw=bh=1/7).
        for (int d = 0; d < 3; d++) {
            S.rows[d] = min(Y0 + d, H - 1);
            S.cols[d] = min(X0 + d, H - 1);
        }
    }
    __syncthreads();

    const int   c    = half * HALF + tid;
    const int   W    = S.HW;
    const float* base = S.fm + S.cbase + (long)c * W * W;

    // Gather the 3x3 patch for this channel into shared memory.
    #pragma unroll
    for (int dy = 0; dy < 3; dy++) {
        const int ro = S.rows[dy] * W;
        #pragma unroll
        for (int dx = 0; dx < 3; dx++)
            patch[tid][dy * 3 + dx] = __ldg(base + ro + S.cols[dx]);
    }

    // Compute all 49 bins from the patch; stage in smem for coalesced writeback.
    const float* pp = patch[tid];
    #pragma unroll
    for (int py = 0; py < POOL; py++) {
        const float ly = S.ly[py];
        const float hy = 1.0f - ly;
        const float vy = S.vy[py];
        const int r0 = S.ry0[py] * 3;
        const int r1 = S.ry1[py] * 3;
        #pragma unroll
        for (int px = 0; px < POOL; px++) {
            const float lx = S.lx[px];
            const float hx = 1.0f - lx;
            const int c0 = S.cx0[px];
            const int c1i = S.cx1[px];
            float v = (hy * hx) * pp[r0 + c0]
                    + (hy * lx) * pp[r0 + c1i]
                    + (ly * hx) * pp[r1 + c0]
                    + (ly * lx) * pp[r1 + c1i];
            stage[tid * (POOL * POOL) + py * POOL + px] = v * (vy * S.vx[px]);
        }
    }
    __syncthreads();

    // Coalesced vectorized writeback: this block owns a contiguous 6272-float run.
    float4*       o4 = reinterpret_cast<float4*>(out + ((long)box * CCH + half * HALF) * (POOL * POOL));
    const float4* s4 = reinterpret_cast<const float4*>(stage);
    #pragma unroll
    for (int i = tid; i < (HALF * POOL * POOL) / 4; i += HALF)
        o4[i] = s4[i];
}

extern "C" void kernel_launch(void* const* d_in, const int* in_sizes, int n_in,
                              void* d_out, int out_size)
{
    const float* boxes = (const float*)d_in[0];
    const float* f2    = (const float*)d_in[1];
    const float* f3    = (const float*)d_in[2];
    const float* f4    = (const float*)d_in[3];
    const float* f5    = (const float*)d_in[4];
    float*       out   = (float*)d_out;

    const int nboxes = in_sizes[0] / 5;
    roi_align_kernel<<<2 * nboxes, HALF>>>(boxes, f2, f3, f4, f5, out, nboxes);
}

// round 3
// speedup vs baseline: 1.7000x; 1.7000x over previous
#include <cuda_runtime.h>
#include <math.h>
#include <stdint.h>

#define POOL 7
#define CCH  256
#define HALF 128   // channels per block (2 blocks per box)

struct BoxShared {
    const float* fm;
    long  cbase;            // batch offset: b * C * H * W
    int   W;                // H == W for each level
    int   rowoff[3];        // clamped row * W (pre-multiplied)
    int   xal;              // 2-aligned window start, window = 4 floats
    int   o[3];             // column offsets within window for patch cols 0..2
    float Wy[POOL][3];      // dense row weights (validity folded in)
    float Wx[POOL][3];      // dense col weights (validity folded in)
};

__global__ void __launch_bounds__(HALF, 8) roi_align_kernel(
    const float* __restrict__ boxes,
    const float* __restrict__ f2,
    const float* __restrict__ f3,
    const float* __restrict__ f4,
    const float* __restrict__ f5,
    float* __restrict__ out)
{
    __shared__ BoxShared S;
    __shared__ __align__(16) float stage[HALF * POOL * POOL];   // 25088 B

    const int box  = blockIdx.x >> 1;
    const int half = blockIdx.x & 1;
    const int tid  = threadIdx.x;

    if (tid == 0) {
        const float bf = boxes[box * 5 + 0];
        const float c1 = boxes[box * 5 + 1];
        const float c2 = boxes[box * 5 + 2];
        const float c3 = boxes[box * 5 + 3];
        const float c4 = boxes[box * 5 + 4];

        // roi level: 4 + log2(sqrt(h*w) / (224/1024)), round-half-even, clip [2,5]
        const float h = c3 - c1;
        const float w = c4 - c2;
        float lvlf = 4.0f + log2f(sqrtf(h * w) / 0.21875f);
        int lvl = (int)rintf(lvlf);
        lvl = max(2, min(5, lvl));

        const float* fm = (lvl == 2) ? f2 : (lvl == 3) ? f3 : (lvl == 4) ? f4 : f5;
        const int   H     = 1024 >> lvl;          // 256,128,64,32
        const float scale = 1.0f / (float)(1 << lvl);

        S.fm    = fm;
        S.W     = H;
        S.cbase = (long)((int)bf) * CCH * H * H;

        // _roi_align interprets rois cols as (x1,y1,x2,y2): x from boxes cols 1,3; y from 2,4.
        const float ax1 = c1 * scale, ay1 = c2 * scale;
        const float ax2 = c3 * scale, ay2 = c4 * scale;
        const float rw = fmaxf(ax2 - ax1, 1.0f);
        const float rh = fmaxf(ay2 - ay1, 1.0f);
        const float bw = rw / (float)POOL;
        const float bh = rh / (float)POOL;

        int X0 = 0, Y0 = 0;
        for (int p = 0; p < POOL; p++) {
            const float pc = (float)p + 0.5f;

            // y axis
            float y  = ay1 + pc * bh;
            float vy = (y > -1.0f && y < (float)H) ? 1.0f : 0.0f;
            float ycl = fminf(fmaxf(y, 0.0f), (float)(H - 1));
            int   y0  = (int)floorf(ycl);
            int   y1i = min(y0 + 1, H - 1);
            if (p == 0) Y0 = y0;                 // ys monotone increasing
            float ly = ycl - (float)y0;
            float hy = 1.0f - ly;
            S.Wy[p][0] = 0.0f; S.Wy[p][1] = 0.0f; S.Wy[p][2] = 0.0f;
            S.Wy[p][y0  - Y0] += vy * hy;
            S.Wy[p][y1i - Y0] += vy * ly;

            // x axis
            float x  = ax1 + pc * bw;
            float vx = (x > -1.0f && x < (float)H) ? 1.0f : 0.0f;
            float xcl = fminf(fmaxf(x, 0.0f), (float)(H - 1));
            int   x0  = (int)floorf(xcl);
            int   x1i = min(x0 + 1, H - 1);
            if (p == 0) X0 = x0;
            float lx = xcl - (float)x0;
            float hx = 1.0f - lx;
            S.Wx[p][0] = 0.0f; S.Wx[p][1] = 0.0f; S.Wx[p][2] = 0.0f;
            S.Wx[p][x0  - X0] += vx * hx;
            S.Wx[p][x1i - X0] += vx * lx;
        }
        // Patch: 3 rows x 3 cols (bin grid spans <1 px). Rows clamp individually.
        for (int d = 0; d < 3; d++)
            S.rowoff[d] = min(Y0 + d, H - 1) * H;
        // 2-aligned 4-wide load window fully inside the row.
        int xal = min(X0 & ~1, H - 4);
        S.xal = xal;
        for (int j = 0; j < 3; j++)
            S.o[j] = min(X0 + j, H - 1) - xal;   // in [0,3]
    }
    __syncthreads();

    const int c = half * HALF + tid;
    const float* base = S.fm + S.cbase + (long)c * S.W * S.W + S.xal;

    const int o0 = S.o[0], o1 = S.o[1], o2 = S.o[2];

    // Gather 3 rows x 4-wide window with float2 loads; select the 3 patch cols.
    float p0[3], p1[3], p2[3];
    {
        #pragma unroll
        for (int r = 0; r < 3; r++) {
            const float* rp = base + S.rowoff[r];
            float2 a = *(const float2*)(rp);
            float2 b = *(const float2*)(rp + 2);
            float v0 = a.x, v1 = a.y, v2 = b.x, v3 = b.y;
            float* pr = (r == 0) ? p0 : (r == 1) ? p1 : p2;
            pr[0] = (o0 == 0) ? v0 : (o0 == 1) ? v1 : (o0 == 2) ? v2 : v3;
            pr[1] = (o1 == 0) ? v0 : (o1 == 1) ? v1 : (o1 == 2) ? v2 : v3;
            pr[2] = (o2 == 0) ? v0 : (o2 == 1) ? v1 : (o2 == 2) ? v2 : v3;
        }
    }

    // Hoist Wx into registers (21 broadcast LDS total).
    float wx[POOL][3];
    #pragma unroll
    for (int px = 0; px < POOL; px++) {
        wx[px][0] = S.Wx[px][0];
        wx[px][1] = S.Wx[px][1];
        wx[px][2] = S.Wx[px][2];
    }

    float* st = stage + tid * (POOL * POOL);
    #pragma unroll
    for (int py = 0; py < POOL; py++) {
        const float wy0 = S.Wy[py][0], wy1 = S.Wy[py][1], wy2 = S.Wy[py][2];
        const float ty0 = wy0 * p0[0] + wy1 * p1[0] + wy2 * p2[0];
        const float ty1 = wy0 * p0[1] + wy1 * p1[1] + wy2 * p2[1];
        const float ty2 = wy0 * p0[2] + wy1 * p1[2] + wy2 * p2[2];
        #pragma unroll
        for (int px = 0; px < POOL; px++)
            st[py * POOL + px] = wx[px][0] * ty0 + wx[px][1] * ty1 + wx[px][2] * ty2;
    }

    // Make generic-proxy smem writes visible to the async proxy, then TMA bulk store.
    asm volatile("fence.proxy.async.shared::cta;" ::: "memory");
    __syncthreads();

    if (tid == 0) {
        unsigned int saddr;
        asm("{ .reg .u64 t; cvta.to.shared.u64 t, %1; cvt.u32.u64 %0, t; }"
            : "=r"(saddr) : "l"(stage));
        const float* dst = out + ((long)box * CCH + half * HALF) * (POOL * POOL);
        asm volatile(
            "cp.async.bulk.global.shared::cta.bulk_group [%0], [%1], %2;"
            :: "l"(dst), "r"(saddr), "r"(HALF * POOL * POOL * 4) : "memory");
        asm volatile("cp.async.bulk.commit_group;" ::: "memory");
        asm volatile("cp.async.bulk.wait_group 0;" ::: "memory");
    }
}

extern "C" void kernel_launch(void* const* d_in, const int* in_sizes, int n_in,
                              void* d_out, int out_size)
{
    const float* boxes = (const float*)d_in[0];
    const float* f2    = (const float*)d_in[1];
    const float* f3    = (const float*)d_in[2];
    const float* f4    = (const float*)d_in[3];
    const float* f5    = (const float*)d_in[4];
    float*       out   = (float*)d_out;

    const int nboxes = in_sizes[0] / 5;
    roi_align_kernel<<<2 * nboxes, HALF>>>(boxes, f2, f3, f4, f5, out);
}